// round 10
// baseline (speedup 1.0000x reference)
#include <cuda_runtime.h>
#include <cuda_fp16.h>
#include <math.h>

// Problem constants (fixed shapes)
#define B_    8
#define LAT_  128
#define H_    1024
#define K_    294
#define N_    100000
#define E_    1600000
#define TAU_  0.5f
#define HALFX 64.0f      // 0.5 * XSIZE
#define CH_   24         // B_*3 channels per node
#define CHP_  32         // padded fp16 mirror channels (64B rows)
#define CAP_  64         // bucket capacity per node (mean deg 16, sigma 4)

// ---------------- scratch (device globals; no allocation allowed) -------------
__device__ float g_act0[B_ * H_];
__device__ float g_act1[B_ * H_];
__device__ __align__(16) float g_C[K_ * CH_];        // C[k][ch], ch = b*3 + d
__device__ __align__(16) float  g_fA[N_ * CH_];      // f32 master ping
__device__ __align__(16) float  g_fB[N_ * CH_];      // f32 master pong
__device__ __align__(16) __half g_fhA[(size_t)N_ * CHP_];  // fp16 mirror ping (padded)
__device__ __align__(16) __half g_fhB[(size_t)N_ * CHP_];  // fp16 mirror pong (padded)
__device__ __align__(16) int2   g_bkt[(size_t)N_ * CAP_];  // {src, w bits} buckets
__device__ int   g_count[N_];
__device__ float g_wsum[N_];
__device__ float g_rdeg[N_];
__device__ float g_regacc;
__device__ int   g_is64;

// ---------------- edge index accessor (dtype-robust) --------------------------
__device__ __forceinline__ int edge_idx(const void* ei, int is64, long long pos) {
    if (is64) return (int)((const long long*)ei)[pos];
    return ((const int*)ei)[pos];
}

// ---------------- init (+ dtype probe on thread 0) ----------------------------
__global__ void init_kernel(const void* __restrict__ ei) {
    int i = blockIdx.x * blockDim.x + threadIdx.x;
    if (i < N_) { g_count[i] = 0; g_wsum[i] = 0.0f; }
    if (i == 0) {
        g_regacc = 0.0f;
        const long long* p = (const long long*)ei;
        int ok = 1;
#pragma unroll 4
        for (int t = 0; t < 64; t++) {
            long long v = p[t];
            if (v < 0 || v >= N_) { ok = 0; break; }
        }
        g_is64 = ok;
    }
}

// ---------------- single-pass bucket fill + weighted degree --------------------
__device__ __forceinline__ void red1(float* p, float a) {
    asm volatile("red.global.add.f32 [%0], %1;" :: "l"(p), "f"(a) : "memory");
}

__global__ void fill_kernel(const void* __restrict__ ei,
                            const float* __restrict__ w) {
    int e = blockIdx.x * blockDim.x + threadIdx.x;
    if (e >= E_) return;
    int is64 = g_is64;
    int s = edge_idx(ei, is64, e);
    int d = edge_idx(ei, is64, (long long)E_ + e);
    float we = w[e];
    int pos = atomicAdd(&g_count[d], 1);
    if (pos < CAP_) g_bkt[(size_t)d * CAP_ + pos] = make_int2(s, __float_as_int(we));
    red1(&g_wsum[d], we);
}

// ---------------- MLP layer: batch-fused, W loaded once ------------------------
// Block = 256 threads = 8 warps; warp wid = k-slice (8-way k-split).
// Warp lanes: jj = lane&7 (output col j0+jj), kk = lane>>3 (k stride 4).
// x[8][Kin] preloaded to smem; each W element used in 8 FFMAs.
__global__ __launch_bounds__(256) void mlp_kernel(const float* __restrict__ in,
                           const float* __restrict__ W,
                           const float* __restrict__ bias,
                           const float* __restrict__ resid,
                           float* __restrict__ out,
                           int Kin, int Jout) {
    __shared__ float xs[B_ * H_ > 8192 ? 8192 : B_ * H_];   // 32KB max
    __shared__ float part[8][8][B_];                        // [wid][jj][b]
    int lane = threadIdx.x & 31, wid = threadIdx.x >> 5;
    int jj = lane & 7, kk = lane >> 3;
    int j0 = blockIdx.x * 8;

    // preload x[8][Kin] (row-major b*Kin+k) via float4
    int totF4 = (B_ * Kin) >> 2;
    for (int i = threadIdx.x; i < totF4; i += 256)
        reinterpret_cast<float4*>(xs)[i] = reinterpret_cast<const float4*>(in)[i];
    __syncthreads();

    int kLen = Kin >> 3;
    int kb = wid * kLen;
    const float* Wp = W + j0 + jj;

    float acc[B_];
#pragma unroll
    for (int b = 0; b < B_; b++) acc[b] = 0.0f;

#pragma unroll 4
    for (int k = kb + kk; k < kb + kLen; k += 4) {
        float wv = Wp[(size_t)k * Jout];
#pragma unroll
        for (int b = 0; b < B_; b++)
            acc[b] += xs[b * Kin + k] * wv;
    }
    // reduce over kk (lanes 8, 16 apart)
#pragma unroll
    for (int b = 0; b < B_; b++) {
        acc[b] += __shfl_xor_sync(0xffffffffu, acc[b], 8);
        acc[b] += __shfl_xor_sync(0xffffffffu, acc[b], 16);
    }
    if (lane < 8) {
#pragma unroll
        for (int b = 0; b < B_; b++) part[wid][jj][b] = acc[b];
    }
    __syncthreads();
    // final reduce: 64 threads, t = jo*8 + b
    if (threadIdx.x < 64) {
        int jo = threadIdx.x >> 3;
        int b  = threadIdx.x & 7;
        int j  = j0 + jo;
        float v = bias[j];
#pragma unroll
        for (int wsum = 0; wsum < 8; wsum++) v += part[wsum][jo][b];
        if (resid) v += resid[b * Jout + j];
        out[b * Jout + j] = fmaxf(v, 0.0f);
    }
}

// ---------------- coefficient heads + reg --------------------------------------
__global__ void head_kernel(const float* __restrict__ h,
                            const float* __restrict__ Wx, const float* __restrict__ bx,
                            const float* __restrict__ Wy, const float* __restrict__ by,
                            const float* __restrict__ Wz, const float* __restrict__ bz) {
    int warpId = (blockIdx.x * blockDim.x + threadIdx.x) >> 5;
    int lane   = threadIdx.x & 31;
    const int JBLK = 37;
    if (warpId >= 3 * B_ * JBLK) return;
    int d   = warpId / (B_ * JBLK);
    int rem = warpId % (B_ * JBLK);
    int b   = rem / JBLK;
    int j0  = (rem % JBLK) << 3;
    int jj  = lane & 7;
    int kk  = lane >> 3;
    int j   = j0 + jj;

    const float* W  = (d == 0) ? Wx : (d == 1) ? Wy : Wz;
    const float* bb = (d == 0) ? bx : (d == 1) ? by : bz;
    const float* hr = h + b * H_;

    float acc = 0.0f;
    if (j < K_) {
#pragma unroll 8
        for (int k = kk; k < H_; k += 4) {
            acc += hr[k] * W[(size_t)k * K_ + j];
        }
    }
    acc += __shfl_xor_sync(0xffffffffu, acc, 8);
    acc += __shfl_xor_sync(0xffffffffu, acc, 16);

    float vv = 0.0f;
    if (lane < 8) {
        int jo = j0 + lane;
        if (jo < K_) {
            float c = acc + bb[jo];
            g_C[jo * CH_ + b * 3 + d] = c;
            vv = c * c;
        }
    }
#pragma unroll
    for (int off = 16; off > 0; off >>= 1)
        vv += __shfl_xor_sync(0xffffffffu, vv, off);
    if (lane == 0) atomicAdd(&g_regacc, vv);
}

// ---------------- GEMM: fA[n][ch] = sum_k (64*C[k][ch]) * Z[k][n] ---------------
union F4U { float4 v; unsigned long long u[2]; };

__device__ __forceinline__ void ffma2(unsigned long long& d,
                                      unsigned long long a,
                                      unsigned long long b) {
    asm("fma.rn.f32x2 %0, %1, %2, %0;" : "+l"(d) : "l"(a), "l"(b));
}
__device__ __forceinline__ unsigned long long dup2(float x) {
    unsigned long long r;
    asm("mov.b64 %0, {%1, %1};" : "=l"(r) : "r"(__float_as_uint(x)));
    return r;
}
__device__ __forceinline__ float lo32(unsigned long long u) {
    return __uint_as_float((unsigned)u);
}
__device__ __forceinline__ float hi32(unsigned long long u) {
    return __uint_as_float((unsigned)(u >> 32));
}

__global__ __launch_bounds__(256) void gemm_kernel(const float* __restrict__ Z) {
    __shared__ float4 Cs[K_ * 6];
    for (int i = threadIdx.x; i < K_ * 6; i += 256) {
        float4 c = reinterpret_cast<const float4*>(g_C)[i];
        Cs[i] = make_float4(HALFX * c.x, HALFX * c.y, HALFX * c.z, HALFX * c.w);
    }
    __syncthreads();

    int n0 = (blockIdx.x * 256 + threadIdx.x) * 2;
    if (n0 >= N_) return;

    unsigned long long accA[12], accB[12];
#pragma unroll
    for (int p = 0; p < 12; p++) { accA[p] = 0ull; accB[p] = 0ull; }

    const float* zp = Z + n0;
#pragma unroll 2
    for (int k = 0; k < K_; k++) {
        float2 z2 = *reinterpret_cast<const float2*>(zp + (size_t)k * N_);
        unsigned long long zx = dup2(z2.x);
        unsigned long long zy = dup2(z2.y);
        const float4* crow = &Cs[k * 6];
#pragma unroll
        for (int c4 = 0; c4 < 6; c4++) {
            F4U cv; cv.v = crow[c4];
            ffma2(accA[c4*2+0], zx, cv.u[0]);
            ffma2(accA[c4*2+1], zx, cv.u[1]);
            ffma2(accB[c4*2+0], zy, cv.u[0]);
            ffma2(accB[c4*2+1], zy, cv.u[1]);
        }
    }
    float4*  f0 = reinterpret_cast<float4*>(g_fA + (size_t)n0 * CH_);
    float4*  f1 = reinterpret_cast<float4*>(g_fA + (size_t)(n0 + 1) * CH_);
    __half2* h0 = reinterpret_cast<__half2*>(g_fhA + (size_t)n0 * CHP_);
    __half2* h1 = reinterpret_cast<__half2*>(g_fhA + (size_t)(n0 + 1) * CHP_);
#pragma unroll
    for (int c4 = 0; c4 < 6; c4++) {
        float4 v0 = make_float4(lo32(accA[c4*2]), hi32(accA[c4*2]),
                                lo32(accA[c4*2+1]), hi32(accA[c4*2+1]));
        float4 v1 = make_float4(lo32(accB[c4*2]), hi32(accB[c4*2]),
                                lo32(accB[c4*2+1]), hi32(accB[c4*2+1]));
        f0[c4] = v0;  f1[c4] = v1;
        h0[c4*2+0] = __floats2half2_rn(v0.x, v0.y);
        h0[c4*2+1] = __floats2half2_rn(v0.z, v0.w);
        h1[c4*2+0] = __floats2half2_rn(v1.x, v1.y);
        h1[c4*2+1] = __floats2half2_rn(v1.z, v1.w);
    }
    __half2 zz = __floats2half2_rn(0.f, 0.f);
#pragma unroll
    for (int p = 12; p < 16; p++) { h0[p] = zz; h1[p] = zz; }
    g_rdeg[n0]     = TAU_ / fmaxf(g_wsum[n0], 1e-6f);
    g_rdeg[n0 + 1] = TAU_ / fmaxf(g_wsum[n0 + 1], 1e-6f);
}

// ---------------- gather: 4 threads/node, 8-edge chunk prefetch -----------------
// Per chunk: load 4x int4 bucket entries UNCONDITIONALLY (array fully allocated),
// mask invalid with s=0/w=0, issue 8 independent f-row loads, then accumulate.
__device__ __forceinline__ void acc8q(uint4 r, float wgt, float* A) {
    float2 f;
    f = __half22float2(*reinterpret_cast<__half2*>(&r.x)); A[0] += wgt*f.x; A[1] += wgt*f.y;
    f = __half22float2(*reinterpret_cast<__half2*>(&r.y)); A[2] += wgt*f.x; A[3] += wgt*f.y;
    f = __half22float2(*reinterpret_cast<__half2*>(&r.z)); A[4] += wgt*f.x; A[5] += wgt*f.y;
    f = __half22float2(*reinterpret_cast<__half2*>(&r.w)); A[6] += wgt*f.x; A[7] += wgt*f.y;
}

__global__ __launch_bounds__(256) void gather_kernel(const __half* __restrict__ fh_src,
                                                     const float*  __restrict__ f_src,
                                                     float*  __restrict__ f_dst,
                                                     __half* __restrict__ fh_dst,
                                                     float* __restrict__ out_final,
                                                     int out_size) {
    int idx = blockIdx.x * blockDim.x + threadIdx.x;
    if (idx >= N_ * 4) return;
    int n = idx >> 2;
    int q = idx & 3;

    if (q == 3) {
        if (out_final == nullptr) {
            uint4 z = make_uint4(0u, 0u, 0u, 0u);
            *reinterpret_cast<uint4*>(fh_dst + (size_t)n * CHP_ + 24) = z;
        }
        return;
    }

    int cnt = g_count[n];
    cnt = (cnt > CAP_) ? CAP_ : cnt;
    const int4* b4 = reinterpret_cast<const int4*>(g_bkt + (size_t)n * CAP_);
    const __half* base = fh_src + q * 8;

    float acc[8];
#pragma unroll
    for (int c = 0; c < 8; c++) acc[c] = 0.0f;

    for (int c0 = 0; c0 < cnt; c0 += 8) {
        int4 p[4];
#pragma unroll
        for (int i = 0; i < 4; i++) p[i] = b4[(c0 >> 1) + i];
        int   s[8];
        float w[8];
#pragma unroll
        for (int i = 0; i < 4; i++) {
            bool v0 = (c0 + 2*i)     < cnt;
            bool v1 = (c0 + 2*i + 1) < cnt;
            s[2*i]   = v0 ? p[i].x : 0;
            w[2*i]   = v0 ? __int_as_float(p[i].y) : 0.0f;
            s[2*i+1] = v1 ? p[i].z : 0;
            w[2*i+1] = v1 ? __int_as_float(p[i].w) : 0.0f;
        }
        uint4 r[8];
#pragma unroll
        for (int i = 0; i < 8; i++)
            r[i] = *reinterpret_cast<const uint4*>(base + (size_t)s[i] * CHP_);
#pragma unroll
        for (int i = 0; i < 8; i++)
            acc8q(r[i], w[i], acc);
    }

    float rd = g_rdeg[n];
    size_t moff = (size_t)n * CH_ + q * 8;
    const float4* fo = reinterpret_cast<const float4*>(f_src + moff);
    float4 pa = fo[0], pb = fo[1];
    float o0 = 0.5f*pa.x + rd*acc[0], o1 = 0.5f*pa.y + rd*acc[1];
    float o2 = 0.5f*pa.z + rd*acc[2], o3 = 0.5f*pa.w + rd*acc[3];
    float o4 = 0.5f*pb.x + rd*acc[4], o5 = 0.5f*pb.y + rd*acc[5];
    float o6 = 0.5f*pb.z + rd*acc[6], o7 = 0.5f*pb.w + rd*acc[7];

    if (out_final == nullptr) {
        float4* fd = reinterpret_cast<float4*>(f_dst + moff);
        fd[0] = make_float4(o0, o1, o2, o3);
        fd[1] = make_float4(o4, o5, o6, o7);
        __half2 hh[4];
        hh[0] = __floats2half2_rn(o0, o1);
        hh[1] = __floats2half2_rn(o2, o3);
        hh[2] = __floats2half2_rn(o4, o5);
        hh[3] = __floats2half2_rn(o6, o7);
        *reinterpret_cast<uint4*>(fh_dst + (size_t)n * CHP_ + q * 8) =
            *reinterpret_cast<uint4*>(hh);
    } else {
        float o[8] = {o0, o1, o2, o3, o4, o5, o6, o7};
        int ch0 = q * 8;
#pragma unroll
        for (int t = 0; t < 8; t++) {
            int ch = ch0 + t;
            int b  = ch / 3;
            int dm = ch - b * 3;
            out_final[(size_t)b * (N_ * 3) + n * 3 + dm] = o[t];
        }
        if (idx == 0 && out_size > B_ * N_ * 3) {
            out_final[(size_t)B_ * N_ * 3] = 1e-4f * sqrtf(g_regacc);
        }
    }
}

// ---------------- launch --------------------------------------------------------
extern "C" void kernel_launch(void* const* d_in, const int* in_sizes, int n_in,
                              void* d_out, int out_size) {
    const float* latent = (const float*)d_in[0];
    const float* W0 = (const float*)d_in[1];   const float* b0 = (const float*)d_in[2];
    const float* W1 = (const float*)d_in[3];   const float* b1 = (const float*)d_in[4];
    const float* W2 = (const float*)d_in[5];   const float* b2 = (const float*)d_in[6];
    const float* W3 = (const float*)d_in[7];   const float* b3 = (const float*)d_in[8];
    const float* Wx = (const float*)d_in[9];   const float* bx = (const float*)d_in[10];
    const float* Wy = (const float*)d_in[11];  const float* by = (const float*)d_in[12];
    const float* Wz = (const float*)d_in[13];  const float* bz = (const float*)d_in[14];
    const float* Z  = (const float*)d_in[15];
    const float* ew = (const float*)d_in[16];
    const void*  ei = d_in[17];
    float* out = (float*)d_out;

    float *act0, *act1;
    cudaGetSymbolAddress((void**)&act0, g_act0);
    cudaGetSymbolAddress((void**)&act1, g_act1);
    float *fA, *fB;
    cudaGetSymbolAddress((void**)&fA, g_fA);
    cudaGetSymbolAddress((void**)&fB, g_fB);
    __half *fhA, *fhB;
    cudaGetSymbolAddress((void**)&fhA, g_fhA);
    cudaGetSymbolAddress((void**)&fhB, g_fhB);

    int gridN = (N_ + 255) / 256;
    int gridE = (E_ + 255) / 256;

    // bucket build (single edge pass)
    init_kernel<<<gridN, 256>>>(ei);
    fill_kernel<<<gridE, 256>>>(ei, ew);

    // MLP decode: batch-fused, grid = Jout/8 blocks
    mlp_kernel<<<H_ / 8, 256>>>(latent, W0, b0, nullptr, act0, LAT_, H_);
    mlp_kernel<<<H_ / 8, 256>>>(act0, W1, b1, act0, act1, H_, H_);
    mlp_kernel<<<H_ / 8, 256>>>(act1, W2, b2, act1, act0, H_, H_);
    mlp_kernel<<<H_ / 8, 256>>>(act0, W3, b3, act0, act1, H_, H_);

    // heads
    int warpsH = 3 * B_ * 37;
    int gridH  = (warpsH * 32 + 255) / 256;
    head_kernel<<<gridH, 256>>>(act1, Wx, bx, Wy, by, Wz, bz);

    // dense expansion -> g_fA (f32) + g_fhA (fp16 padded); epilogue computes rdeg
    int gridG = ((N_ / 2) + 255) / 256;
    gemm_kernel<<<gridG, 256>>>(Z);

    // 3 diffusion steps; last one writes the transposed output directly
    int gridGa = (N_ * 4 + 255) / 256;
    gather_kernel<<<gridGa, 256>>>(fhA, fA, fB, fhB, nullptr, 0);
    gather_kernel<<<gridGa, 256>>>(fhB, fB, fA, fhA, nullptr, 0);
    gather_kernel<<<gridGa, 256>>>(fhA, fA, nullptr, nullptr, out, out_size);
}

// round 12
// speedup vs baseline: 1.0970x; 1.0970x over previous
#include <cuda_runtime.h>
#include <cuda_fp16.h>
#include <math.h>

// Problem constants (fixed shapes)
#define B_    8
#define LAT_  128
#define H_    1024
#define K_    294
#define N_    100000
#define E_    1600000
#define TAU_  0.5f
#define HALFX 64.0f      // 0.5 * XSIZE
#define CH_   24         // B_*3 channels per node
#define CHP_  32         // padded fp16 mirror channels (64B rows)
#define CAP_  64         // bucket capacity per node (mean deg 16, sigma 4)
#define ZB    14         // gemm z-batch depth (294 = 21 * 14)

// ---------------- scratch (device globals; no allocation allowed) -------------
// Invariant: g_count/g_wsum/g_regacc are ZERO at kernel_launch entry
// (zero-initialized at load; cleanup_kernel re-zeroes at the end of each call).
__device__ float g_act0[B_ * H_];
__device__ float g_act1[B_ * H_];
__device__ __align__(16) float g_C[K_ * CH_];        // C[k][ch], ch = b*3 + d
__device__ __align__(16) float  g_fA[N_ * CH_];      // f32 master ping
__device__ __align__(16) float  g_fB[N_ * CH_];      // f32 master pong
__device__ __align__(16) __half g_fhA[(size_t)N_ * CHP_];  // fp16 mirror ping (padded)
__device__ __align__(16) __half g_fhB[(size_t)N_ * CHP_];  // fp16 mirror pong (padded)
__device__ __align__(16) int2   g_bkt[(size_t)N_ * CAP_];  // {src, w bits} buckets
__device__ int   g_count[N_];
__device__ float g_wsum[N_];
__device__ float g_regacc;
__device__ int   g_is64;

// ---------------- edge index accessor (dtype-robust) --------------------------
__device__ __forceinline__ int edge_idx(const void* ei, int is64, long long pos) {
    if (is64) return (int)((const long long*)ei)[pos];
    return ((const int*)ei)[pos];
}

// ---------------- single-pass bucket fill + weighted degree --------------------
__device__ __forceinline__ void red1(float* p, float a) {
    asm volatile("red.global.add.f32 [%0], %1;" :: "l"(p), "f"(a) : "memory");
}

__global__ void fill_kernel(const void* __restrict__ ei,
                            const float* __restrict__ w) {
    int e = blockIdx.x * blockDim.x + threadIdx.x;
    if (e >= E_) return;
    int is64 = g_is64;
    int s = edge_idx(ei, is64, e);
    int d = edge_idx(ei, is64, (long long)E_ + e);
    float we = w[e];
    int pos = atomicAdd(&g_count[d], 1);
    if (pos < CAP_) g_bkt[(size_t)d * CAP_ + pos] = make_int2(s, __float_as_int(we));
    red1(&g_wsum[d], we);
}

// ---------------- MLP layer (R5 version, measured 11.3us/layer) -----------------
// Block = 256 threads = 8 warps = 2 j-groups x 4 k-quarters. Cross-warp smem reduce.
// ei_probe != null on the FIRST layer only: thread 0 runs the dtype probe
// (result consumed by fill_kernel, which launches after this kernel completes).
__global__ __launch_bounds__(256) void mlp_kernel(const float* __restrict__ in,
                           const float* __restrict__ W,
                           const float* __restrict__ bias,
                           const float* __restrict__ resid,
                           float* __restrict__ out,
                           int Kin, int Jout,
                           const void* __restrict__ ei_probe) {
    if (ei_probe && blockIdx.x == 0 && threadIdx.x == 0) {
        const long long* p = (const long long*)ei_probe;
        int ok = 1;
#pragma unroll 4
        for (int t = 0; t < 64; t++) {
            long long v = p[t];
            if (v < 0 || v >= N_) { ok = 0; break; }
        }
        g_is64 = ok;
    }
    __shared__ float part[2][4][8];
    int lane = threadIdx.x & 31, wid = threadIdx.x >> 5;
    int jg = wid >> 2, kq = wid & 3;
    int jBlocks = Jout >> 4;
    int b  = blockIdx.x / jBlocks;
    int j0 = (blockIdx.x % jBlocks) * 16 + jg * 8;
    int jj = lane & 7;
    int kk = lane >> 3;
    int kLen = Kin >> 2;
    int kBeg = kq * kLen;

    const float* inr = in + b * Kin;
    const float* Wp  = W + j0 + jj;
    float acc = 0.0f;
#pragma unroll 8
    for (int k = kBeg + kk; k < kBeg + kLen; k += 4) {
        acc += inr[k] * Wp[(size_t)k * Jout];
    }
    acc += __shfl_xor_sync(0xffffffffu, acc, 8);
    acc += __shfl_xor_sync(0xffffffffu, acc, 16);
    if (lane < 8) part[jg][kq][lane] = acc;
    __syncthreads();
    if (kq == 0 && lane < 8) {
        int j = j0 + lane;
        float v = part[jg][0][lane] + part[jg][1][lane]
                + part[jg][2][lane] + part[jg][3][lane] + bias[j];
        if (resid) v += resid[b * Jout + j];
        out[b * Jout + j] = fmaxf(v, 0.0f);
    }
}

// ---------------- coefficient heads + reg --------------------------------------
__global__ void head_kernel(const float* __restrict__ h,
                            const float* __restrict__ Wx, const float* __restrict__ bx,
                            const float* __restrict__ Wy, const float* __restrict__ by,
                            const float* __restrict__ Wz, const float* __restrict__ bz) {
    int warpId = (blockIdx.x * blockDim.x + threadIdx.x) >> 5;
    int lane   = threadIdx.x & 31;
    const int JBLK = 37;
    if (warpId >= 3 * B_ * JBLK) return;
    int d   = warpId / (B_ * JBLK);
    int rem = warpId % (B_ * JBLK);
    int b   = rem / JBLK;
    int j0  = (rem % JBLK) << 3;
    int jj  = lane & 7;
    int kk  = lane >> 3;
    int j   = j0 + jj;

    const float* W  = (d == 0) ? Wx : (d == 1) ? Wy : Wz;
    const float* bb = (d == 0) ? bx : (d == 1) ? by : bz;
    const float* hr = h + b * H_;

    float acc = 0.0f;
    if (j < K_) {
#pragma unroll 8
        for (int k = kk; k < H_; k += 4) {
            acc += hr[k] * W[(size_t)k * K_ + j];
        }
    }
    acc += __shfl_xor_sync(0xffffffffu, acc, 8);
    acc += __shfl_xor_sync(0xffffffffu, acc, 16);

    float vv = 0.0f;
    if (lane < 8) {
        int jo = j0 + lane;
        if (jo < K_) {
            float c = acc + bb[jo];
            g_C[jo * CH_ + b * 3 + d] = c;
            vv = c * c;
        }
    }
#pragma unroll
    for (int off = 16; off > 0; off >>= 1)
        vv += __shfl_xor_sync(0xffffffffu, vv, off);
    if (lane == 0) atomicAdd(&g_regacc, vv);
}

// ---------------- GEMM: fA[n][ch] = sum_k (64*C[k][ch]) * Z[k][n] ---------------
// FFMA2 packed channel pairs + 14-deep z load batching (independent stream loads
// to hide DRAM latency at the low 196-block occupancy).
union F4U { float4 v; unsigned long long u[2]; };

__device__ __forceinline__ void ffma2(unsigned long long& d,
                                      unsigned long long a,
                                      unsigned long long b) {
    asm("fma.rn.f32x2 %0, %1, %2, %0;" : "+l"(d) : "l"(a), "l"(b));
}
__device__ __forceinline__ unsigned long long dup2(float x) {
    unsigned long long r;
    asm("mov.b64 %0, {%1, %1};" : "=l"(r) : "r"(__float_as_uint(x)));
    return r;
}
__device__ __forceinline__ float lo32(unsigned long long u) {
    return __uint_as_float((unsigned)u);
}
__device__ __forceinline__ float hi32(unsigned long long u) {
    return __uint_as_float((unsigned)(u >> 32));
}

__global__ __launch_bounds__(256) void gemm_kernel(const float* __restrict__ Z) {
    __shared__ float4 Cs[K_ * 6];
    for (int i = threadIdx.x; i < K_ * 6; i += 256) {
        float4 c = reinterpret_cast<const float4*>(g_C)[i];
        Cs[i] = make_float4(HALFX * c.x, HALFX * c.y, HALFX * c.z, HALFX * c.w);
    }
    __syncthreads();

    int n0 = (blockIdx.x * 256 + threadIdx.x) * 2;
    if (n0 >= N_) return;

    unsigned long long accA[12], accB[12];
#pragma unroll
    for (int p = 0; p < 12; p++) { accA[p] = 0ull; accB[p] = 0ull; }

    const float* zp = Z + n0;
    for (int k0 = 0; k0 < K_; k0 += ZB) {
        float2 z2[ZB];
#pragma unroll
        for (int i = 0; i < ZB; i++)
            z2[i] = *reinterpret_cast<const float2*>(zp + (size_t)(k0 + i) * N_);
#pragma unroll
        for (int i = 0; i < ZB; i++) {
            unsigned long long zx = dup2(z2[i].x);
            unsigned long long zy = dup2(z2[i].y);
            const float4* crow = &Cs[(k0 + i) * 6];
#pragma unroll
            for (int c4 = 0; c4 < 6; c4++) {
                F4U cv; cv.v = crow[c4];
                ffma2(accA[c4*2+0], zx, cv.u[0]);
                ffma2(accA[c4*2+1], zx, cv.u[1]);
                ffma2(accB[c4*2+0], zy, cv.u[0]);
                ffma2(accB[c4*2+1], zy, cv.u[1]);
            }
        }
    }
    float4*  f0 = reinterpret_cast<float4*>(g_fA + (size_t)n0 * CH_);
    float4*  f1 = reinterpret_cast<float4*>(g_fA + (size_t)(n0 + 1) * CH_);
    __half2* h0 = reinterpret_cast<__half2*>(g_fhA + (size_t)n0 * CHP_);
    __half2* h1 = reinterpret_cast<__half2*>(g_fhA + (size_t)(n0 + 1) * CHP_);
#pragma unroll
    for (int c4 = 0; c4 < 6; c4++) {
        float4 v0 = make_float4(lo32(accA[c4*2]), hi32(accA[c4*2]),
                                lo32(accA[c4*2+1]), hi32(accA[c4*2+1]));
        float4 v1 = make_float4(lo32(accB[c4*2]), hi32(accB[c4*2]),
                                lo32(accB[c4*2+1]), hi32(accB[c4*2+1]));
        f0[c4] = v0;  f1[c4] = v1;
        h0[c4*2+0] = __floats2half2_rn(v0.x, v0.y);
        h0[c4*2+1] = __floats2half2_rn(v0.z, v0.w);
        h1[c4*2+0] = __floats2half2_rn(v1.x, v1.y);
        h1[c4*2+1] = __floats2half2_rn(v1.z, v1.w);
    }
    __half2 zz = __floats2half2_rn(0.f, 0.f);
#pragma unroll
    for (int p = 12; p < 16; p++) { h0[p] = zz; h1[p] = zz; }
}

// ---------------- gather: 4 threads/node on 64B-padded mirror (R9 version) ------
// rd computed from g_wsum directly (no rdeg array, no fill->gemm dependency).
__device__ __forceinline__ void acc8q(uint4 r, float wgt, float* A) {
    float2 f;
    f = __half22float2(*reinterpret_cast<__half2*>(&r.x)); A[0] += wgt*f.x; A[1] += wgt*f.y;
    f = __half22float2(*reinterpret_cast<__half2*>(&r.y)); A[2] += wgt*f.x; A[3] += wgt*f.y;
    f = __half22float2(*reinterpret_cast<__half2*>(&r.z)); A[4] += wgt*f.x; A[5] += wgt*f.y;
    f = __half22float2(*reinterpret_cast<__half2*>(&r.w)); A[6] += wgt*f.x; A[7] += wgt*f.y;
}

__global__ __launch_bounds__(256) void gather_kernel(const __half* __restrict__ fh_src,
                                                     const float*  __restrict__ f_src,
                                                     float*  __restrict__ f_dst,
                                                     __half* __restrict__ fh_dst,
                                                     float* __restrict__ out_final,
                                                     int out_size) {
    int idx = blockIdx.x * blockDim.x + threadIdx.x;
    if (idx >= N_ * 4) return;
    int n = idx >> 2;
    int q = idx & 3;

    if (q == 3) {
        if (out_final == nullptr) {
            uint4 z = make_uint4(0u, 0u, 0u, 0u);
            *reinterpret_cast<uint4*>(fh_dst + (size_t)n * CHP_ + 24) = z;
        }
        return;
    }

    int cnt = g_count[n];
    cnt = (cnt > CAP_) ? CAP_ : cnt;
    const int2* bkt = g_bkt + (size_t)n * CAP_;
    const __half* base = fh_src + q * 8;

    float acc[8];
#pragma unroll
    for (int c = 0; c < 8; c++) acc[c] = 0.0f;

    int j = 0;
    for (; j + 1 < cnt; j += 2) {
        int2 swa = bkt[j];
        int2 swb = bkt[j + 1];
        float wa = __int_as_float(swa.y);
        float wb = __int_as_float(swb.y);
        uint4 ra = *reinterpret_cast<const uint4*>(base + (size_t)swa.x * CHP_);
        uint4 rb = *reinterpret_cast<const uint4*>(base + (size_t)swb.x * CHP_);
        acc8q(ra, wa, acc);
        acc8q(rb, wb, acc);
    }
    if (j < cnt) {
        int2 sw = bkt[j];
        float wgt = __int_as_float(sw.y);
        uint4 r = *reinterpret_cast<const uint4*>(base + (size_t)sw.x * CHP_);
        acc8q(r, wgt, acc);
    }

    float rd = TAU_ / fmaxf(g_wsum[n], 1e-6f);
    size_t moff = (size_t)n * CH_ + q * 8;
    const float4* fo = reinterpret_cast<const float4*>(f_src + moff);
    float4 pa = fo[0], pb = fo[1];
    float o0 = 0.5f*pa.x + rd*acc[0], o1 = 0.5f*pa.y + rd*acc[1];
    float o2 = 0.5f*pa.z + rd*acc[2], o3 = 0.5f*pa.w + rd*acc[3];
    float o4 = 0.5f*pb.x + rd*acc[4], o5 = 0.5f*pb.y + rd*acc[5];
    float o6 = 0.5f*pb.z + rd*acc[6], o7 = 0.5f*pb.w + rd*acc[7];

    if (out_final == nullptr) {
        float4* fd = reinterpret_cast<float4*>(f_dst + moff);
        fd[0] = make_float4(o0, o1, o2, o3);
        fd[1] = make_float4(o4, o5, o6, o7);
        __half2 hh[4];
        hh[0] = __floats2half2_rn(o0, o1);
        hh[1] = __floats2half2_rn(o2, o3);
        hh[2] = __floats2half2_rn(o4, o5);
        hh[3] = __floats2half2_rn(o6, o7);
        *reinterpret_cast<uint4*>(fh_dst + (size_t)n * CHP_ + q * 8) =
            *reinterpret_cast<uint4*>(hh);
    } else {
        float o[8] = {o0, o1, o2, o3, o4, o5, o6, o7};
        int ch0 = q * 8;
#pragma unroll
        for (int t = 0; t < 8; t++) {
            int ch = ch0 + t;
            int b  = ch / 3;
            int dm = ch - b * 3;
            out_final[(size_t)b * (N_ * 3) + n * 3 + dm] = o[t];
        }
        if (idx == 0 && out_size > B_ * N_ * 3) {
            out_final[(size_t)B_ * N_ * 3] = 1e-4f * sqrtf(g_regacc);
        }
    }
}

// ---------------- cleanup: restore zero-invariant for next call/replay ----------
__global__ void cleanup_kernel() {
    int i = blockIdx.x * blockDim.x + threadIdx.x;
    if (i < N_) { g_count[i] = 0; g_wsum[i] = 0.0f; }
    if (i == 0) g_regacc = 0.0f;
}

// ---------------- launch --------------------------------------------------------
extern "C" void kernel_launch(void* const* d_in, const int* in_sizes, int n_in,
                              void* d_out, int out_size) {
    const float* latent = (const float*)d_in[0];
    const float* W0 = (const float*)d_in[1];   const float* b0 = (const float*)d_in[2];
    const float* W1 = (const float*)d_in[3];   const float* b1 = (const float*)d_in[4];
    const float* W2 = (const float*)d_in[5];   const float* b2 = (const float*)d_in[6];
    const float* W3 = (const float*)d_in[7];   const float* b3 = (const float*)d_in[8];
    const float* Wx = (const float*)d_in[9];   const float* bx = (const float*)d_in[10];
    const float* Wy = (const float*)d_in[11];  const float* by = (const float*)d_in[12];
    const float* Wz = (const float*)d_in[13];  const float* bz = (const float*)d_in[14];
    const float* Z  = (const float*)d_in[15];
    const float* ew = (const float*)d_in[16];
    const void*  ei = d_in[17];
    float* out = (float*)d_out;

    float *act0, *act1;
    cudaGetSymbolAddress((void**)&act0, g_act0);
    cudaGetSymbolAddress((void**)&act1, g_act1);
    float *fA, *fB;
    cudaGetSymbolAddress((void**)&fA, g_fA);
    cudaGetSymbolAddress((void**)&fB, g_fB);
    __half *fhA, *fhB;
    cudaGetSymbolAddress((void**)&fhA, g_fhA);
    cudaGetSymbolAddress((void**)&fhB, g_fhB);

    int gridN = (N_ + 255) / 256;
    int gridE = (E_ + 255) / 256;
    int gridL = B_ * (H_ >> 4);          // 512 blocks
    int gridGa = (N_ * 4 + 255) / 256;

    // (1) mlp1 + embedded dtype probe (writes g_is64 before fill launches)
    mlp_kernel<<<gridL, 256>>>(latent, W0, b0, nullptr, act0, LAT_, H_, ei);
    // (2) bucket build (counts/wsum zero by invariant)
    fill_kernel<<<gridE, 256>>>(ei, ew);
    // (3-5) remaining MLP layers
    mlp_kernel<<<gridL, 256>>>(act0, W1, b1, act0, act1, H_, H_, nullptr);
    mlp_kernel<<<gridL, 256>>>(act1, W2, b2, act1, act0, H_, H_, nullptr);
    mlp_kernel<<<gridL, 256>>>(act0, W3, b3, act0, act1, H_, H_, nullptr);
    // (6) DIAGNOSTIC PROBE — identical to gather step 1, stale inputs, outputs
    // fully overwritten by (9). Positioned so ncu (-s 5 -c 1) captures it.
    gather_kernel<<<gridGa, 256>>>(fhA, fA, fB, fhB, nullptr, 0);
    // (7) heads
    int warpsH = 3 * B_ * 37;
    int gridH  = (warpsH * 32 + 255) / 256;
    head_kernel<<<gridH, 256>>>(act1, Wx, bx, Wy, by, Wz, bz);
    // (8) dense expansion -> g_fA (f32) + g_fhA (fp16 padded)
    int gridG = ((N_ / 2) + 255) / 256;
    gemm_kernel<<<gridG, 256>>>(Z);
    // (9-11) 3 diffusion steps; last writes transposed output
    gather_kernel<<<gridGa, 256>>>(fhA, fA, fB, fhB, nullptr, 0);
    gather_kernel<<<gridGa, 256>>>(fhB, fB, fA, fhA, nullptr, 0);
    gather_kernel<<<gridGa, 256>>>(fhA, fA, nullptr, nullptr, out, out_size);
    // (12) restore zero-invariant for the next graph replay
    cleanup_kernel<<<gridN, 256>>>();
}

// round 13
// speedup vs baseline: 1.2647x; 1.1528x over previous
#include <cuda_runtime.h>
#include <cuda_fp16.h>
#include <math.h>

// Problem constants (fixed shapes)
#define B_    8
#define LAT_  128
#define H_    1024
#define K_    294
#define N_    100000
#define E_    1600000
#define TAU_  0.5f
#define HALFX 64.0f      // 0.5 * XSIZE
#define CH_   24         // B_*3 channels per node
#define CHP_  32         // padded fp16 mirror channels (64B rows)
#define CAP_  64         // bucket capacity per node (mean deg 16, sigma 4)
#define ZB    14         // gemm z-batch depth (294 = 21 * 14)

// ---------------- scratch (device globals; no allocation allowed) -------------
// Invariant: g_count/g_regacc are ZERO at kernel_launch entry
// (zero-initialized at load; cleanup_kernel re-zeroes at the end of each call).
__device__ float g_act0[B_ * H_];
__device__ float g_act1[B_ * H_];
__device__ __align__(16) float g_C[K_ * CH_];        // C[k][ch], ch = b*3 + d
__device__ __align__(16) float  g_fA[N_ * CH_];      // f32 master ping
__device__ __align__(16) float  g_fB[N_ * CH_];      // f32 master pong
__device__ __align__(16) __half g_fhA[(size_t)N_ * CHP_];  // fp16 mirror ping (padded)
__device__ __align__(16) __half g_fhB[(size_t)N_ * CHP_];  // fp16 mirror pong (padded)
__device__ __align__(16) int2   g_bkt[(size_t)N_ * CAP_];  // {src, w bits} buckets
__device__ int   g_count[N_];
__device__ float g_regacc;
__device__ int   g_is64;

// ---------------- edge index accessor (dtype-robust) --------------------------
__device__ __forceinline__ int edge_idx(const void* ei, int is64, long long pos) {
    if (is64) return (int)((const long long*)ei)[pos];
    return ((const int*)ei)[pos];
}

// ---------------- single-pass bucket fill --------------------------------------
__global__ void fill_kernel(const void* __restrict__ ei,
                            const float* __restrict__ w) {
    int e = blockIdx.x * blockDim.x + threadIdx.x;
    if (e >= E_) return;
    int is64 = g_is64;
    int s = edge_idx(ei, is64, e);
    int d = edge_idx(ei, is64, (long long)E_ + e);
    float we = w[e];
    int pos = atomicAdd(&g_count[d], 1);
    if (pos < CAP_) g_bkt[(size_t)d * CAP_ + pos] = make_int2(s, __float_as_int(we));
}

// ---------------- MLP layer: 8-way k-split, 8 outputs/block ---------------------
// Block = 256 threads = 8 warps; warp wid = k-eighth (32-iteration chains).
// Warp lanes: jj = lane&7 (output), kk = lane>>3 (k stride 4).
// ei_probe != null on the FIRST layer only: thread 0 runs the dtype probe.
__global__ __launch_bounds__(256) void mlp_kernel(const float* __restrict__ in,
                           const float* __restrict__ W,
                           const float* __restrict__ bias,
                           const float* __restrict__ resid,
                           float* __restrict__ out,
                           int Kin, int Jout,
                           const void* __restrict__ ei_probe) {
    if (ei_probe && blockIdx.x == 0 && threadIdx.x == 0) {
        const long long* p = (const long long*)ei_probe;
        int ok = 1;
#pragma unroll 4
        for (int t = 0; t < 64; t++) {
            long long v = p[t];
            if (v < 0 || v >= N_) { ok = 0; break; }
        }
        g_is64 = ok;
    }
    __shared__ float part[8][8];      // [wid][jj]
    int lane = threadIdx.x & 31, wid = threadIdx.x >> 5;
    int jBlocks = Jout >> 3;
    int b  = blockIdx.x / jBlocks;
    int j0 = (blockIdx.x % jBlocks) * 8;
    int jj = lane & 7;
    int kk = lane >> 3;
    int kLen = Kin >> 3;
    int kBeg = wid * kLen;

    const float* inr = in + b * Kin;
    const float* Wp  = W + j0 + jj;
    float acc = 0.0f;
#pragma unroll 8
    for (int k = kBeg + kk; k < kBeg + kLen; k += 4) {
        acc += inr[k] * Wp[(size_t)k * Jout];
    }
    acc += __shfl_xor_sync(0xffffffffu, acc, 8);
    acc += __shfl_xor_sync(0xffffffffu, acc, 16);
    if (lane < 8) part[wid][lane] = acc;
    __syncthreads();
    if (threadIdx.x < 8) {
        int j = j0 + threadIdx.x;
        float v = bias[j];
#pragma unroll
        for (int s = 0; s < 8; s++) v += part[s][threadIdx.x];
        if (resid) v += resid[b * Jout + j];
        out[b * Jout + j] = fmaxf(v, 0.0f);
    }
}

// ---------------- coefficient heads + reg --------------------------------------
__global__ void head_kernel(const float* __restrict__ h,
                            const float* __restrict__ Wx, const float* __restrict__ bx,
                            const float* __restrict__ Wy, const float* __restrict__ by,
                            const float* __restrict__ Wz, const float* __restrict__ bz) {
    int warpId = (blockIdx.x * blockDim.x + threadIdx.x) >> 5;
    int lane   = threadIdx.x & 31;
    const int JBLK = 37;
    if (warpId >= 3 * B_ * JBLK) return;
    int d   = warpId / (B_ * JBLK);
    int rem = warpId % (B_ * JBLK);
    int b   = rem / JBLK;
    int j0  = (rem % JBLK) << 3;
    int jj  = lane & 7;
    int kk  = lane >> 3;
    int j   = j0 + jj;

    const float* W  = (d == 0) ? Wx : (d == 1) ? Wy : Wz;
    const float* bb = (d == 0) ? bx : (d == 1) ? by : bz;
    const float* hr = h + b * H_;

    float acc = 0.0f;
    if (j < K_) {
#pragma unroll 8
        for (int k = kk; k < H_; k += 4) {
            acc += hr[k] * W[(size_t)k * K_ + j];
        }
    }
    acc += __shfl_xor_sync(0xffffffffu, acc, 8);
    acc += __shfl_xor_sync(0xffffffffu, acc, 16);

    float vv = 0.0f;
    if (lane < 8) {
        int jo = j0 + lane;
        if (jo < K_) {
            float c = acc + bb[jo];
            g_C[jo * CH_ + b * 3 + d] = c;
            vv = c * c;
        }
    }
#pragma unroll
    for (int off = 16; off > 0; off >>= 1)
        vv += __shfl_xor_sync(0xffffffffu, vv, off);
    if (lane == 0) atomicAdd(&g_regacc, vv);
}

// ---------------- GEMM: fA[n][ch] = sum_k (64*C[k][ch]) * Z[k][n] ---------------
// FFMA2 packed channel pairs + 14-deep z load batching.
union F4U { float4 v; unsigned long long u[2]; };

__device__ __forceinline__ void ffma2(unsigned long long& d,
                                      unsigned long long a,
                                      unsigned long long b) {
    asm("fma.rn.f32x2 %0, %1, %2, %0;" : "+l"(d) : "l"(a), "l"(b));
}
__device__ __forceinline__ unsigned long long dup2(float x) {
    unsigned long long r;
    asm("mov.b64 %0, {%1, %1};" : "=l"(r) : "r"(__float_as_uint(x)));
    return r;
}
__device__ __forceinline__ float lo32(unsigned long long u) {
    return __uint_as_float((unsigned)u);
}
__device__ __forceinline__ float hi32(unsigned long long u) {
    return __uint_as_float((unsigned)(u >> 32));
}

__global__ __launch_bounds__(256) void gemm_kernel(const float* __restrict__ Z) {
    __shared__ float4 Cs[K_ * 6];
    for (int i = threadIdx.x; i < K_ * 6; i += 256) {
        float4 c = reinterpret_cast<const float4*>(g_C)[i];
        Cs[i] = make_float4(HALFX * c.x, HALFX * c.y, HALFX * c.z, HALFX * c.w);
    }
    __syncthreads();

    int n0 = (blockIdx.x * 256 + threadIdx.x) * 2;
    if (n0 >= N_) return;

    unsigned long long accA[12], accB[12];
#pragma unroll
    for (int p = 0; p < 12; p++) { accA[p] = 0ull; accB[p] = 0ull; }

    const float* zp = Z + n0;
    for (int k0 = 0; k0 < K_; k0 += ZB) {
        float2 z2[ZB];
#pragma unroll
        for (int i = 0; i < ZB; i++)
            z2[i] = *reinterpret_cast<const float2*>(zp + (size_t)(k0 + i) * N_);
#pragma unroll
        for (int i = 0; i < ZB; i++) {
            unsigned long long zx = dup2(z2[i].x);
            unsigned long long zy = dup2(z2[i].y);
            const float4* crow = &Cs[(k0 + i) * 6];
#pragma unroll
            for (int c4 = 0; c4 < 6; c4++) {
                F4U cv; cv.v = crow[c4];
                ffma2(accA[c4*2+0], zx, cv.u[0]);
                ffma2(accA[c4*2+1], zx, cv.u[1]);
                ffma2(accB[c4*2+0], zy, cv.u[0]);
                ffma2(accB[c4*2+1], zy, cv.u[1]);
            }
        }
    }
    float4*  f0 = reinterpret_cast<float4*>(g_fA + (size_t)n0 * CH_);
    float4*  f1 = reinterpret_cast<float4*>(g_fA + (size_t)(n0 + 1) * CH_);
    __half2* h0 = reinterpret_cast<__half2*>(g_fhA + (size_t)n0 * CHP_);
    __half2* h1 = reinterpret_cast<__half2*>(g_fhA + (size_t)(n0 + 1) * CHP_);
#pragma unroll
    for (int c4 = 0; c4 < 6; c4++) {
        float4 v0 = make_float4(lo32(accA[c4*2]), hi32(accA[c4*2]),
                                lo32(accA[c4*2+1]), hi32(accA[c4*2+1]));
        float4 v1 = make_float4(lo32(accB[c4*2]), hi32(accB[c4*2]),
                                lo32(accB[c4*2+1]), hi32(accB[c4*2+1]));
        f0[c4] = v0;  f1[c4] = v1;
        h0[c4*2+0] = __floats2half2_rn(v0.x, v0.y);
        h0[c4*2+1] = __floats2half2_rn(v0.z, v0.w);
        h1[c4*2+0] = __floats2half2_rn(v1.x, v1.y);
        h1[c4*2+1] = __floats2half2_rn(v1.z, v1.w);
    }
    __half2 zz = __floats2half2_rn(0.f, 0.f);
#pragma unroll
    for (int p = 12; p < 16; p++) { h0[p] = zz; h1[p] = zz; }
}

// ---------------- gather: 4 threads/node on 64B-padded mirror -------------------
// wsum computed inline from bucket weights (fill no longer accumulates it).
__device__ __forceinline__ void acc8q(uint4 r, float wgt, float* A) {
    float2 f;
    f = __half22float2(*reinterpret_cast<__half2*>(&r.x)); A[0] += wgt*f.x; A[1] += wgt*f.y;
    f = __half22float2(*reinterpret_cast<__half2*>(&r.y)); A[2] += wgt*f.x; A[3] += wgt*f.y;
    f = __half22float2(*reinterpret_cast<__half2*>(&r.z)); A[4] += wgt*f.x; A[5] += wgt*f.y;
    f = __half22float2(*reinterpret_cast<__half2*>(&r.w)); A[6] += wgt*f.x; A[7] += wgt*f.y;
}

__global__ __launch_bounds__(256) void gather_kernel(const __half* __restrict__ fh_src,
                                                     const float*  __restrict__ f_src,
                                                     float*  __restrict__ f_dst,
                                                     __half* __restrict__ fh_dst,
                                                     float* __restrict__ out_final,
                                                     int out_size) {
    int idx = blockIdx.x * blockDim.x + threadIdx.x;
    if (idx >= N_ * 4) return;
    int n = idx >> 2;
    int q = idx & 3;

    if (q == 3) {
        if (out_final == nullptr) {
            uint4 z = make_uint4(0u, 0u, 0u, 0u);
            *reinterpret_cast<uint4*>(fh_dst + (size_t)n * CHP_ + 24) = z;
        }
        return;
    }

    int cnt = g_count[n];
    cnt = (cnt > CAP_) ? CAP_ : cnt;
    const int2* bkt = g_bkt + (size_t)n * CAP_;
    const __half* base = fh_src + q * 8;

    float acc[8];
#pragma unroll
    for (int c = 0; c < 8; c++) acc[c] = 0.0f;
    float ws = 0.0f;

    int j = 0;
    for (; j + 1 < cnt; j += 2) {
        int2 swa = bkt[j];
        int2 swb = bkt[j + 1];
        float wa = __int_as_float(swa.y);
        float wb = __int_as_float(swb.y);
        uint4 ra = *reinterpret_cast<const uint4*>(base + (size_t)swa.x * CHP_);
        uint4 rb = *reinterpret_cast<const uint4*>(base + (size_t)swb.x * CHP_);
        ws += wa + wb;
        acc8q(ra, wa, acc);
        acc8q(rb, wb, acc);
    }
    if (j < cnt) {
        int2 sw = bkt[j];
        float wgt = __int_as_float(sw.y);
        uint4 r = *reinterpret_cast<const uint4*>(base + (size_t)sw.x * CHP_);
        ws += wgt;
        acc8q(r, wgt, acc);
    }

    float rd = TAU_ / fmaxf(ws, 1e-6f);
    size_t moff = (size_t)n * CH_ + q * 8;
    const float4* fo = reinterpret_cast<const float4*>(f_src + moff);
    float4 pa = fo[0], pb = fo[1];
    float o0 = 0.5f*pa.x + rd*acc[0], o1 = 0.5f*pa.y + rd*acc[1];
    float o2 = 0.5f*pa.z + rd*acc[2], o3 = 0.5f*pa.w + rd*acc[3];
    float o4 = 0.5f*pb.x + rd*acc[4], o5 = 0.5f*pb.y + rd*acc[5];
    float o6 = 0.5f*pb.z + rd*acc[6], o7 = 0.5f*pb.w + rd*acc[7];

    if (out_final == nullptr) {
        float4* fd = reinterpret_cast<float4*>(f_dst + moff);
        fd[0] = make_float4(o0, o1, o2, o3);
        fd[1] = make_float4(o4, o5, o6, o7);
        __half2 hh[4];
        hh[0] = __floats2half2_rn(o0, o1);
        hh[1] = __floats2half2_rn(o2, o3);
        hh[2] = __floats2half2_rn(o4, o5);
        hh[3] = __floats2half2_rn(o6, o7);
        *reinterpret_cast<uint4*>(fh_dst + (size_t)n * CHP_ + q * 8) =
            *reinterpret_cast<uint4*>(hh);
    } else {
        float o[8] = {o0, o1, o2, o3, o4, o5, o6, o7};
        int ch0 = q * 8;
#pragma unroll
        for (int t = 0; t < 8; t++) {
            int ch = ch0 + t;
            int b  = ch / 3;
            int dm = ch - b * 3;
            out_final[(size_t)b * (N_ * 3) + n * 3 + dm] = o[t];
        }
        if (idx == 0 && out_size > B_ * N_ * 3) {
            out_final[(size_t)B_ * N_ * 3] = 1e-4f * sqrtf(g_regacc);
        }
    }
}

// ---------------- cleanup: restore zero-invariant for next call/replay ----------
__global__ void cleanup_kernel() {
    int i = blockIdx.x * blockDim.x + threadIdx.x;
    if (i < N_) g_count[i] = 0;
    if (i == 0) g_regacc = 0.0f;
}

// ---------------- launch --------------------------------------------------------
extern "C" void kernel_launch(void* const* d_in, const int* in_sizes, int n_in,
                              void* d_out, int out_size) {
    const float* latent = (const float*)d_in[0];
    const float* W0 = (const float*)d_in[1];   const float* b0 = (const float*)d_in[2];
    const float* W1 = (const float*)d_in[3];   const float* b1 = (const float*)d_in[4];
    const float* W2 = (const float*)d_in[5];   const float* b2 = (const float*)d_in[6];
    const float* W3 = (const float*)d_in[7];   const float* b3 = (const float*)d_in[8];
    const float* Wx = (const float*)d_in[9];   const float* bx = (const float*)d_in[10];
    const float* Wy = (const float*)d_in[11];  const float* by = (const float*)d_in[12];
    const float* Wz = (const float*)d_in[13];  const float* bz = (const float*)d_in[14];
    const float* Z  = (const float*)d_in[15];
    const float* ew = (const float*)d_in[16];
    const void*  ei = d_in[17];
    float* out = (float*)d_out;

    float *act0, *act1;
    cudaGetSymbolAddress((void**)&act0, g_act0);
    cudaGetSymbolAddress((void**)&act1, g_act1);
    float *fA, *fB;
    cudaGetSymbolAddress((void**)&fA, g_fA);
    cudaGetSymbolAddress((void**)&fB, g_fB);
    __half *fhA, *fhB;
    cudaGetSymbolAddress((void**)&fhA, g_fhA);
    cudaGetSymbolAddress((void**)&fhB, g_fhB);

    int gridN = (N_ + 255) / 256;
    int gridE = (E_ + 255) / 256;
    int gridL = B_ * (H_ >> 3);          // 1024 blocks (8 outputs/block)
    int gridGa = (N_ * 4 + 255) / 256;

    // (1) mlp1 + embedded dtype probe (writes g_is64 before fill launches)
    mlp_kernel<<<gridL, 256>>>(latent, W0, b0, nullptr, act0, LAT_, H_, ei);
    // (2) bucket build (counts zero by invariant)
    fill_kernel<<<gridE, 256>>>(ei, ew);
    // (3-5) remaining MLP layers
    mlp_kernel<<<gridL, 256>>>(act0, W1, b1, act0, act1, H_, H_, nullptr);
    mlp_kernel<<<gridL, 256>>>(act1, W2, b2, act1, act0, H_, H_, nullptr);
    mlp_kernel<<<gridL, 256>>>(act0, W3, b3, act0, act1, H_, H_, nullptr);
    // (6) heads
    int warpsH = 3 * B_ * 37;
    int gridH  = (warpsH * 32 + 255) / 256;
    head_kernel<<<gridH, 256>>>(act1, Wx, bx, Wy, by, Wz, bz);
    // (7) dense expansion -> g_fA (f32) + g_fhA (fp16 padded)
    int gridG = ((N_ / 2) + 255) / 256;
    gemm_kernel<<<gridG, 256>>>(Z);
    // (8-10) 3 diffusion steps; last writes transposed output
    gather_kernel<<<gridGa, 256>>>(fhA, fA, fB, fhB, nullptr, 0);
    gather_kernel<<<gridGa, 256>>>(fhB, fB, fA, fhA, nullptr, 0);
    gather_kernel<<<gridGa, 256>>>(fhA, fA, nullptr, nullptr, out, out_size);
    // (11) restore zero-invariant for the next graph replay
    cleanup_kernel<<<gridN, 256>>>();
}